// round 4
// baseline (speedup 1.0000x reference)
#include <cuda_runtime.h>
#include <cuda_bf16.h>

#define B_ 8
#define T_ 256
#define U_ 65
#define D_ 512
#define BTU_ (B_ * T_ * U_)
#define SROW 66                  // padded row stride (floats)
#define PAD 64                   // NEG pad rows front/back in smem tiles
#define RTOT (T_ + 2 * PAD)      // 384

#define NBLK 148                 // <= SM count -> single wave, co-resident
#define DPB  B_                  // 8 dp CTAs
#define LSEB (NBLK - DPB)        // 140 lse CTAs
#define THR  512
#define WPB  (THR / 32)          // 16 warps
#define LSEW (LSEB * WPB)        // 2240 lse warps

#define NEG (-1.0e30f)
#define INV_LN2 1.4426950408889634f
#define LN2 0.6931471805599453f

// Device-global scratch (zero-initialized at load; g_cnt reset to 0 each run).
__device__ float g_blank[B_ * T_ * SROW];
__device__ float g_label[B_ * T_ * SROW];
__device__ int   g_cnt[B_ * T_];

__device__ __forceinline__ float ex2f(float x) {
    float y; asm("ex2.approx.ftz.f32 %0, %1;" : "=f"(y) : "f"(x)); return y;
}
__device__ __forceinline__ float lg2f(float x) {
    float y; asm("lg2.approx.ftz.f32 %0, %1;" : "=f"(y) : "f"(x)); return y;
}
__device__ __forceinline__ float lae2(float a, float b) {  // logaddexp, log2 domain
    float mx = fmaxf(a, b);
    float mn = fminf(a, b);
    return mx + lg2f(1.0f + ex2f(mn - mx));
}

extern __shared__ float s_dyn[];

__global__ void __launch_bounds__(THR, 1)
fused_kernel(const float* __restrict__ logits, const int* __restrict__ targets,
             const int* __restrict__ srcLen, const int* __restrict__ tgtLen,
             float* __restrict__ out) {
    __shared__ int s_ready[T_];

    const int tid = threadIdx.x;
    const int wid = tid >> 5;
    const int lane = tid & 31;

    // ======================= LSE producer CTAs =======================
    if (blockIdx.x >= DPB) {
        const int gw0 = (blockIdx.x - DPB) * WPB + wid;
        for (int r = gw0; r < BTU_; r += LSEW) {
            // t-major enumeration: rows for small t complete first, all batches.
            const int t = r / (B_ * U_);
            const int bu = r - t * (B_ * U_);
            const int b = bu / U_;
            const int u = bu - b * U_;
            const size_t row = (size_t)(b * T_ + t) * U_ + u;

            const float4* row4 = reinterpret_cast<const float4*>(logits + row * D_);
            const float4 v0 = row4[lane];
            const float4 v1 = row4[lane + 32];
            const float4 v2 = row4[lane + 64];
            const float4 v3 = row4[lane + 96];

            float m = v0.x;
            m = fmaxf(m, v0.y); m = fmaxf(m, v0.z); m = fmaxf(m, v0.w);
            m = fmaxf(m, v1.x); m = fmaxf(m, v1.y); m = fmaxf(m, v1.z); m = fmaxf(m, v1.w);
            m = fmaxf(m, v2.x); m = fmaxf(m, v2.y); m = fmaxf(m, v2.z); m = fmaxf(m, v2.w);
            m = fmaxf(m, v3.x); m = fmaxf(m, v3.y); m = fmaxf(m, v3.z); m = fmaxf(m, v3.w);
#pragma unroll
            for (int o = 16; o; o >>= 1) m = fmaxf(m, __shfl_xor_sync(0xffffffffu, m, o));

            float s = 0.f;
            s += __expf(v0.x - m) + __expf(v0.y - m) + __expf(v0.z - m) + __expf(v0.w - m);
            s += __expf(v1.x - m) + __expf(v1.y - m) + __expf(v1.z - m) + __expf(v1.w - m);
            s += __expf(v2.x - m) + __expf(v2.y - m) + __expf(v2.z - m) + __expf(v2.w - m);
            s += __expf(v3.x - m) + __expf(v3.y - m) + __expf(v3.z - m) + __expf(v3.w - m);
#pragma unroll
            for (int o = 16; o; o >>= 1) s += __shfl_xor_sync(0xffffffffu, s, o);

            const float lse = m + __logf(s);
            const float blankLogit = __shfl_sync(0xffffffffu, v3.w, 31);

            if (lane == 0) {
                const int lbl = (u < U_ - 1) ? targets[b * (U_ - 1) + u] : 0;
                const float labelLogit = __ldg(logits + row * D_ + lbl);
                const int gi = (b * T_ + t) * SROW + u;
                g_blank[gi] = (blankLogit - lse) * INV_LN2;
                g_label[gi] = (labelLogit - lse) * INV_LN2;
                if (u == U_ - 1) {              // NEG pad column 65
                    g_blank[gi + 1] = NEG;
                    g_label[gi + 1] = NEG;
                }
                __threadfence();                 // release
                atomicAdd(&g_cnt[b * T_ + t], 1);
            }
        }
        return;
    }

    // ======================= DP consumer CTAs =======================
    const int b = blockIdx.x;
    float* sB = s_dyn;                  // [RTOT * SROW]
    float* sL = s_dyn + RTOT * SROW;

    {   // NEG-fill pad rows; zero smem ready flags.
        const float4 ng = make_float4(NEG, NEG, NEG, NEG);
        float4* sb4 = reinterpret_cast<float4*>(sB);
        float4* sl4 = reinterpret_cast<float4*>(sL);
        const int padQ = (PAD * SROW) / 4;
        const int backQ = ((PAD + T_) * SROW) / 4;
        for (int i = tid; i < padQ; i += THR) {
            sb4[i] = ng;          sl4[i] = ng;
            sb4[backQ + i] = ng;  sl4[backQ + i] = ng;
        }
        for (int i = tid; i < T_; i += THR) s_ready[i] = 0;
    }
    __syncthreads();

    if (wid > 0) {
        // ---- copy engines: warps 1..15 stream rows t = wid-1, +15, ... ----
        for (int t = wid - 1; t < T_; t += WPB - 1) {
            if (lane == 0) {
                while (*(volatile int*)&g_cnt[b * T_ + t] < U_) __nanosleep(40);
            }
            __syncwarp();
            __threadfence();                   // acquire
            const float2* gb = reinterpret_cast<const float2*>(g_blank + (size_t)(b * T_ + t) * SROW);
            const float2* gl = reinterpret_cast<const float2*>(g_label + (size_t)(b * T_ + t) * SROW);
            float2* sb = reinterpret_cast<float2*>(sB + (PAD + t) * SROW);
            float2* sl = reinterpret_cast<float2*>(sL + (PAD + t) * SROW);
#pragma unroll
            for (int i = lane; i < SROW / 2; i += 32) {   // 33 float2 per array
                sb[i] = __ldcg(gb + i);                   // .cg: bypass L1 staleness
                sl[i] = __ldcg(gl + i);
            }
            __syncwarp();
            __threadfence_block();
            if (lane == 0) *(volatile int*)&s_ready[t] = 1;
        }
    } else {
        // ---- dp warp: branchless register wavefront (round-3 math) ----
        const int tE = srcLen[b] - 1;
        const int uE = tgtLen[b];
        const int dE = tE + uE;

        const int u0 = 2 * lane;
        const int u1 = u0 + 1;

        float aE = (lane == 0) ? 0.0f : NEG;
        float aO = NEG;
        float aX = NEG;

        const float* pB0 = sB + (PAD + (1 - u0) - 1) * SROW + u0;
        const float* pL0 = sL + (PAD + (1 - u0)) * SROW + (u0 - 1);
        const float* pB1 = sB + (PAD + (1 - u0) - 2) * SROW + u1;
        const float* pL1 = sL + (PAD + (1 - u0) - 1) * SROW + u0;
        const float* pBx = sB + (PAD + 1 - 65) * SROW + 64;
        const float* pLx = sL + (PAD + 1 - 64) * SROW + 63;

        int t0 = 1 - u0;
        int lastReady = -1;

        for (int d = 1; d <= dE; ++d) {
            const int need = (d < T_) ? d : (T_ - 1);
            if (need > lastReady) {
                for (int rr = lastReady + 1; rr <= need; ++rr) {
                    while (!*(volatile int*)&s_ready[rr]) { }
                }
                __threadfence_block();
                lastReady = need;
            }

            const float xB0 = *pB0;
            const float xL0 = *pL0;
            const float xB1 = *pB1;
            const float xL1 = *pL1;
            const float xBx = *pBx;
            const float xLx = *pLx;

            const float nbr = __shfl_up_sync(0xffffffffu, aO, 1);

            const float rE = lae2(aE + xB0, nbr + xL0);
            const float rO = lae2(aO + xB1, aE + xL1);
            const float rX = lae2(aX + xBx, aO + xLx);

            const bool actE = (unsigned)t0 < (unsigned)T_;
            const bool actO = (unsigned)(t0 - 1) < (unsigned)T_;
            const bool actX = ((unsigned)(d - 64) < (unsigned)T_) && (lane == 31);

            aE = actE ? rE : aE;
            aO = actO ? rO : aO;
            aX = actX ? rX : aX;

            pB0 += SROW; pL0 += SROW; pB1 += SROW; pL1 += SROW; pBx += SROW; pLx += SROW;
            ++t0;
        }

        // Ensure row tE staged (covers degenerate dE < tE impossible, dE==0 case).
        for (int rr = lastReady + 1; rr <= tE; ++rr) {
            while (!*(volatile int*)&s_ready[rr]) { }
        }
        __threadfence_block();

        const bool ownE = (uE == u0);
        const bool ownO = (uE == u1);
        const bool ownX = (uE == 64) && (lane == 31);
        if (ownE || ownO || ownX) {
            float alphaF = ownX ? aX : (ownO ? aO : aE);
            if (dE == 0) alphaF = 0.0f;
            out[b] = -LN2 * (alphaF + sB[(PAD + tE) * SROW + uE]);
        }
    }

    __syncthreads();
    // Reset counters for the next (graph-replayed) run.
    for (int i = tid; i < T_; i += THR) g_cnt[b * T_ + i] = 0;
}

// ---------------------------------------------------------------------------
extern "C" void kernel_launch(void* const* d_in, const int* in_sizes, int n_in,
                              void* d_out, int out_size) {
    const float* logits = (const float*)d_in[0];
    const int* targets = (const int*)d_in[1];
    const int* srcLen = (const int*)d_in[2];
    const int* tgtLen = (const int*)d_in[3];
    float* out = (float*)d_out;

    const int smemBytes = 2 * RTOT * SROW * (int)sizeof(float);  // 202752 B
    cudaFuncSetAttribute(fused_kernel, cudaFuncAttributeMaxDynamicSharedMemorySize, smemBytes);
    fused_kernel<<<NBLK, THR, smemBytes>>>(logits, targets, srcLen, tgtLen, out);
}

// round 6
// speedup vs baseline: 1.2295x; 1.2295x over previous
#include <cuda_runtime.h>
#include <cuda_bf16.h>

#define B_ 8
#define T_ 256
#define U_ 65
#define D_ 512
#define BTU_ (B_ * T_ * U_)
#define SROW 66                  // padded row stride (floats)
#define PAD 64                   // NEG pad rows front/back in dp smem tiles
#define RTOT (T_ + 2 * PAD)      // 384

#define LSE_GRID 888             // 6 CTAs/SM x 148 SMs -> single wave
#define LSE_WARPS (LSE_GRID * 8)

#define NEG (-1.0e30f)
#define INV_LN2 1.4426950408889634f
#define LN2 0.6931471805599453f

// Device-global scratch (module zero-init; g_cnt reset by dp each run).
__device__ float g_blank[B_ * T_ * SROW];
__device__ float g_label[B_ * T_ * SROW];
__device__ int   g_cnt[B_ * T_];

__device__ __forceinline__ float ex2f(float x) {
    float y; asm("ex2.approx.ftz.f32 %0, %1;" : "=f"(y) : "f"(x)); return y;
}
__device__ __forceinline__ float lg2f(float x) {
    float y; asm("lg2.approx.ftz.f32 %0, %1;" : "=f"(y) : "f"(x)); return y;
}
__device__ __forceinline__ float lae2(float a, float b) {  // logaddexp, log2 domain
    float mx = fmaxf(a, b);
    float mn = fminf(a, b);
    return mx + lg2f(1.0f + ex2f(mn - mx));
}

// ---------------------------------------------------------------------------
// LSE producer: persistent single-wave grid (888 CTAs x 256 thr, 0 smem).
// One warp per row, grid-stride over t-major row ids so each batch's rows
// complete roughly in t order. Calls the PDL trigger at entry so the dp
// kernel launches immediately.
// ---------------------------------------------------------------------------
__global__ void __launch_bounds__(256) lse_kernel(const float* __restrict__ logits,
                                                  const int* __restrict__ targets) {
    cudaTriggerProgrammaticLaunchCompletion();

    const int wid = threadIdx.x >> 5;
    const int lane = threadIdx.x & 31;

    for (int r = blockIdx.x * 8 + wid; r < BTU_; r += LSE_WARPS) {
        // t-major: rows for small t are produced first, across all batches.
        const int t = r / (B_ * U_);
        const int bu = r - t * (B_ * U_);
        const int b = bu / U_;
        const int u = bu - b * U_;
        const size_t row = (size_t)(b * T_ + t) * U_ + u;

        const float4* row4 = reinterpret_cast<const float4*>(logits + row * D_);
        const float4 v0 = row4[lane];
        const float4 v1 = row4[lane + 32];
        const float4 v2 = row4[lane + 64];
        const float4 v3 = row4[lane + 96];

        float m = v0.x;
        m = fmaxf(m, v0.y); m = fmaxf(m, v0.z); m = fmaxf(m, v0.w);
        m = fmaxf(m, v1.x); m = fmaxf(m, v1.y); m = fmaxf(m, v1.z); m = fmaxf(m, v1.w);
        m = fmaxf(m, v2.x); m = fmaxf(m, v2.y); m = fmaxf(m, v2.z); m = fmaxf(m, v2.w);
        m = fmaxf(m, v3.x); m = fmaxf(m, v3.y); m = fmaxf(m, v3.z); m = fmaxf(m, v3.w);
#pragma unroll
        for (int o = 16; o; o >>= 1) m = fmaxf(m, __shfl_xor_sync(0xffffffffu, m, o));

        float s = 0.f;
        s += __expf(v0.x - m) + __expf(v0.y - m) + __expf(v0.z - m) + __expf(v0.w - m);
        s += __expf(v1.x - m) + __expf(v1.y - m) + __expf(v1.z - m) + __expf(v1.w - m);
        s += __expf(v2.x - m) + __expf(v2.y - m) + __expf(v2.z - m) + __expf(v2.w - m);
        s += __expf(v3.x - m) + __expf(v3.y - m) + __expf(v3.z - m) + __expf(v3.w - m);
#pragma unroll
        for (int o = 16; o; o >>= 1) s += __shfl_xor_sync(0xffffffffu, s, o);

        const float lse = m + __logf(s);
        const float blankLogit = __shfl_sync(0xffffffffu, v3.w, 31);   // element 511

        if (lane == 0) {
            const int lbl = (u < U_ - 1) ? targets[b * (U_ - 1) + u] : 0;
            const float labelLogit = __ldg(logits + row * D_ + lbl);
            const int gi = (b * T_ + t) * SROW + u;
            g_blank[gi] = (blankLogit - lse) * INV_LN2;    // log2 domain
            g_label[gi] = (labelLogit - lse) * INV_LN2;
            if (u == U_ - 1) {                              // NEG pad column 65
                g_blank[gi + 1] = NEG;
                g_label[gi + 1] = NEG;
            }
            __threadfence();                                // release
            atomicAdd(&g_cnt[b * T_ + t], 1);
        }
    }
}

// ---------------------------------------------------------------------------
// DP consumer: 8 CTAs (one per batch), 256 threads, 202KB dyn smem.
// Launched with PDL -> starts while lse runs. Warps 1..7 spin on g_cnt and
// stream ready rows into NEG-padded smem tiles; warp 0 runs the branchless
// register wavefront.
// ---------------------------------------------------------------------------
extern __shared__ float s_dyn[];

__global__ void __launch_bounds__(256, 1) dp_kernel(const int* __restrict__ srcLen,
                                                    const int* __restrict__ tgtLen,
                                                    float* __restrict__ out) {
    __shared__ int s_ready[T_];

    const int b = blockIdx.x;
    const int tid = threadIdx.x;
    const int wid = tid >> 5;
    const int lane = tid & 31;

    float* sB = s_dyn;                 // [RTOT * SROW]
    float* sL = s_dyn + RTOT * SROW;

    {   // NEG-fill pad rows; zero ready flags.
        const float4 ng = make_float4(NEG, NEG, NEG, NEG);
        float4* sb4 = reinterpret_cast<float4*>(sB);
        float4* sl4 = reinterpret_cast<float4*>(sL);
        const int padQ = (PAD * SROW) / 4;
        const int backQ = ((PAD + T_) * SROW) / 4;
        for (int i = tid; i < padQ; i += 256) {
            sb4[i] = ng;          sl4[i] = ng;
            sb4[backQ + i] = ng;  sl4[backQ + i] = ng;
        }
        for (int i = tid; i < T_; i += 256) s_ready[i] = 0;
    }
    __syncthreads();

    if (wid > 0) {
        // ---- copy engines: warps 1..7 stream rows t = wid-1, +7, ... ----
        for (int t = wid - 1; t < T_; t += 7) {
            if (lane == 0) {
                while (*(volatile int*)&g_cnt[b * T_ + t] < U_) __nanosleep(40);
            }
            __syncwarp();
            __threadfence();               // acquire vs producer's release
            const float2* gb = reinterpret_cast<const float2*>(g_blank + (size_t)(b * T_ + t) * SROW);
            const float2* gl = reinterpret_cast<const float2*>(g_label + (size_t)(b * T_ + t) * SROW);
            float2* sb = reinterpret_cast<float2*>(sB + (PAD + t) * SROW);
            float2* sl = reinterpret_cast<float2*>(sL + (PAD + t) * SROW);
#pragma unroll
            for (int i = lane; i < SROW / 2; i += 32) {   // 33 float2 per array
                sb[i] = __ldcg(gb + i);
                sl[i] = __ldcg(gl + i);
            }
            __syncwarp();
            __threadfence_block();
            if (lane == 0) *(volatile int*)&s_ready[t] = 1;
        }
    } else {
        // ---- dp warp: branchless register wavefront ----
        const int tE = srcLen[b] - 1;
        const int uE = tgtLen[b];
        const int dE = tE + uE;

        const int u0 = 2 * lane;
        const int u1 = u0 + 1;

        float aE = (lane == 0) ? 0.0f : NEG;
        float aO = NEG;
        float aX = NEG;

        const float* pB0 = sB + (PAD + (1 - u0) - 1) * SROW + u0;
        const float* pL0 = sL + (PAD + (1 - u0)) * SROW + (u0 - 1);
        const float* pB1 = sB + (PAD + (1 - u0) - 2) * SROW + u1;
        const float* pL1 = sL + (PAD + (1 - u0) - 1) * SROW + u0;
        const float* pBx = sB + (PAD + 1 - 65) * SROW + 64;
        const float* pLx = sL + (PAD + 1 - 64) * SROW + 63;

        int t0 = 1 - u0;
        int lastReady = -1;

        for (int d = 1; d <= dE; ++d) {
            const int need = (d < T_) ? d : (T_ - 1);
            if (need > lastReady) {
                for (int rr = lastReady + 1; rr <= need; ++rr) {
                    while (!*(volatile int*)&s_ready[rr]) { }
                }
                __threadfence_block();
                lastReady = need;
            }

            const float xB0 = *pB0;
            const float xL0 = *pL0;
            const float xB1 = *pB1;
            const float xL1 = *pL1;
            const float xBx = *pBx;
            const float xLx = *pLx;

            const float nbr = __shfl_up_sync(0xffffffffu, aO, 1);

            const float rE = lae2(aE + xB0, nbr + xL0);
            const float rO = lae2(aO + xB1, aE + xL1);
            const float rX = lae2(aX + xBx, aO + xLx);

            const bool actE = (unsigned)t0 < (unsigned)T_;
            const bool actO = (unsigned)(t0 - 1) < (unsigned)T_;
            const bool actX = ((unsigned)(d - 64) < (unsigned)T_) && (lane == 31);

            aE = actE ? rE : aE;
            aO = actO ? rO : aO;
            aX = actX ? rX : aX;

            pB0 += SROW; pL0 += SROW; pB1 += SROW; pL1 += SROW; pBx += SROW; pLx += SROW;
            ++t0;
        }

        for (int rr = lastReady + 1; rr <= tE; ++rr) {
            while (!*(volatile int*)&s_ready[rr]) { }
        }
        __threadfence_block();

        const bool ownE = (uE == u0);
        const bool ownO = (uE == u1);
        const bool ownX = (uE == 64) && (lane == 31);
        if (ownE || ownO || ownX) {
            float alphaF = ownX ? aX : (ownO ? aO : aE);
            if (dE == 0) alphaF = 0.0f;
            out[b] = -LN2 * (alphaF + sB[(PAD + tE) * SROW + uE]);
        }
    }

    __syncthreads();
    // All producers for batch b have finished (row T-1 consumed). Reset
    // counters for the next graph replay.
    for (int i = tid; i < T_; i += 256) g_cnt[b * T_ + i] = 0;
}

// ---------------------------------------------------------------------------
// Same-stream PDL: lse first (calls trigger at entry; single wave -> trigger
// fires immediately), dp second with programmatic stream serialization so it
// overlaps lse. No stream/event creation -> graph- and guard-safe.
// ---------------------------------------------------------------------------
extern "C" void kernel_launch(void* const* d_in, const int* in_sizes, int n_in,
                              void* d_out, int out_size) {
    const float* logits = (const float*)d_in[0];
    const int* targets = (const int*)d_in[1];
    const int* srcLen = (const int*)d_in[2];
    const int* tgtLen = (const int*)d_in[3];
    float* out = (float*)d_out;

    const int smemBytes = 2 * RTOT * SROW * (int)sizeof(float);  // 202752 B
    cudaFuncSetAttribute(dp_kernel, cudaFuncAttributeMaxDynamicSharedMemorySize, smemBytes);

    lse_kernel<<<LSE_GRID, 256>>>(logits, targets);

    cudaLaunchConfig_t cfg = {};
    cfg.gridDim = dim3(B_, 1, 1);
    cfg.blockDim = dim3(256, 1, 1);
    cfg.dynamicSmemBytes = smemBytes;
    cfg.stream = 0;
    cudaLaunchAttribute attrs[1];
    attrs[0].id = cudaLaunchAttributeProgrammaticStreamSerialization;
    attrs[0].val.programmaticStreamSerializationAllowed = 1;
    cfg.attrs = attrs;
    cfg.numAttrs = 1;
    cudaLaunchKernelEx(&cfg, dp_kernel, srcLen, tgtLen, out);
}

// round 7
// speedup vs baseline: 1.3314x; 1.0829x over previous
#include <cuda_runtime.h>
#include <cuda_bf16.h>

#define B_ 8
#define T_ 256
#define U_ 65
#define D_ 512
#define BTU_ (B_ * T_ * U_)
#define SROW 66                  // padded row stride (floats)
#define PAD 64                   // zero pad rows in front of row 0
#define RTOT 392                 // PAD + 256 + back pad (covers row d+P <= 323)

#define LSE_GRID 888             // 6 CTAs/SM x 148 SMs -> single wave
#define LSE_WARPS (LSE_GRID * 8)
#define PF_DEPTH 4               // prefetch distance in diagonals

#define NEG (-1.0e30f)
#define INV_LN2 1.4426950408889634f
#define LN2 0.6931471805599453f

// Device-global scratch. Pads stay zero forever (never written) -> values read
// there are discarded by activity masks or absorbed by NEG arithmetic.
__device__ float g_blank[B_ * RTOT * SROW];
__device__ float g_label[B_ * RTOT * SROW];
__device__ int   g_cnt[B_ * T_];          // reset to 0 by dp each run

__device__ __forceinline__ float ex2f(float x) {
    float y; asm("ex2.approx.ftz.f32 %0, %1;" : "=f"(y) : "f"(x)); return y;
}
__device__ __forceinline__ float lg2f(float x) {
    float y; asm("lg2.approx.ftz.f32 %0, %1;" : "=f"(y) : "f"(x)); return y;
}
__device__ __forceinline__ float lae2(float a, float b) {  // logaddexp, log2 domain
    float mx = fmaxf(a, b);
    float mn = fminf(a, b);
    return mx + lg2f(1.0f + ex2f(mn - mx));
}

// ---------------------------------------------------------------------------
// LSE producer: persistent single-wave grid (888 x 256, 0 smem). One warp per
// row, grid-stride over t-major row ids; publishes per-(b,t) counters with a
// release-scoped reduction.
// ---------------------------------------------------------------------------
__global__ void __launch_bounds__(256) lse_kernel(const float* __restrict__ logits,
                                                  const int* __restrict__ targets) {
    cudaTriggerProgrammaticLaunchCompletion();

    const int wid = threadIdx.x >> 5;
    const int lane = threadIdx.x & 31;

    for (int r = blockIdx.x * 8 + wid; r < BTU_; r += LSE_WARPS) {
        const int t = r / (B_ * U_);
        const int bu = r - t * (B_ * U_);
        const int b = bu / U_;
        const int u = bu - b * U_;
        const size_t row = (size_t)(b * T_ + t) * U_ + u;

        const float4* row4 = reinterpret_cast<const float4*>(logits + row * D_);
        const float4 v0 = row4[lane];
        const float4 v1 = row4[lane + 32];
        const float4 v2 = row4[lane + 64];
        const float4 v3 = row4[lane + 96];

        float m = v0.x;
        m = fmaxf(m, v0.y); m = fmaxf(m, v0.z); m = fmaxf(m, v0.w);
        m = fmaxf(m, v1.x); m = fmaxf(m, v1.y); m = fmaxf(m, v1.z); m = fmaxf(m, v1.w);
        m = fmaxf(m, v2.x); m = fmaxf(m, v2.y); m = fmaxf(m, v2.z); m = fmaxf(m, v2.w);
        m = fmaxf(m, v3.x); m = fmaxf(m, v3.y); m = fmaxf(m, v3.z); m = fmaxf(m, v3.w);
#pragma unroll
        for (int o = 16; o; o >>= 1) m = fmaxf(m, __shfl_xor_sync(0xffffffffu, m, o));

        float s = 0.f;
        s += __expf(v0.x - m) + __expf(v0.y - m) + __expf(v0.z - m) + __expf(v0.w - m);
        s += __expf(v1.x - m) + __expf(v1.y - m) + __expf(v1.z - m) + __expf(v1.w - m);
        s += __expf(v2.x - m) + __expf(v2.y - m) + __expf(v2.z - m) + __expf(v2.w - m);
        s += __expf(v3.x - m) + __expf(v3.y - m) + __expf(v3.z - m) + __expf(v3.w - m);
#pragma unroll
        for (int o = 16; o; o >>= 1) s += __shfl_xor_sync(0xffffffffu, s, o);

        const float lse = m + __logf(s);
        const float blankLogit = __shfl_sync(0xffffffffu, v3.w, 31);   // element 511

        if (lane == 0) {
            const int lbl = (u < U_ - 1) ? targets[b * (U_ - 1) + u] : 0;
            const float labelLogit = __ldg(logits + row * D_ + lbl);
            const size_t gi = ((size_t)b * RTOT + PAD + t) * SROW + u;
            g_blank[gi] = (blankLogit - lse) * INV_LN2;    // log2 domain
            g_label[gi] = (labelLogit - lse) * INV_LN2;
            if (u == U_ - 1) {                              // NEG pad column 65
                g_blank[gi + 1] = NEG;
                g_label[gi + 1] = NEG;
            }
            // release: prior stores visible (at L2) before count bump
            asm volatile("red.release.gpu.global.add.u32 [%0], 1;"
                         :: "l"(g_cnt + b * T_ + t) : "memory");
        }
    }
}

// ---------------------------------------------------------------------------
// Watermark probe: verify up to 32 contiguous rows at once.
// Returns new contiguous watermark (rows <= cw confirmed complete).
// ---------------------------------------------------------------------------
__device__ __forceinline__ int probe32(const int* cnt, int cw, int lane) {
    int r = cw + 1 + lane;
    r = r > (T_ - 1) ? (T_ - 1) : r;
    int c;
    asm volatile("ld.acquire.gpu.global.u32 %0, [%1];" : "=r"(c) : "l"(cnt + r));
    const unsigned done = __ballot_sync(0xffffffffu, c >= U_);
    const unsigned nd = ~done;
    const int adv = nd ? (__ffs(nd) - 1) : 32;
    int ncw = cw + adv;
    return ncw > (T_ - 1) ? (T_ - 1) : ncw;
}

#define GATE(RN)                                          \
    while (cw < (RN)) {                                   \
        const int ncw = probe32(cnt, cw, lane);           \
        if (ncw == cw) __nanosleep(50);                   \
        cw = ncw;                                         \
    }

// ---------------------------------------------------------------------------
// DP: 8 CTAs x 32 threads, zero smem. Branchless register wavefront reading
// blank/label directly from L2 with a PF_DEPTH-diagonal prefetch pipeline.
// ---------------------------------------------------------------------------
__global__ void __launch_bounds__(32, 1) dp_kernel(const int* __restrict__ srcLen,
                                                   const int* __restrict__ tgtLen,
                                                   float* __restrict__ out) {
    const int b = blockIdx.x;
    const int lane = threadIdx.x;

    const int* cnt = g_cnt + b * T_;
    const float* gB = g_blank + (size_t)b * RTOT * SROW;
    const float* gL = g_label + (size_t)b * RTOT * SROW;

    const int tE = srcLen[b] - 1;
    const int uE = tgtLen[b];
    const int dE = tE + uE;

    const int u0 = 2 * lane;
    const int u1 = u0 + 1;

    float aE = (lane == 0) ? 0.0f : NEG;   // u = u0
    float aO = NEG;                        // u = u1
    float aX = NEG;                        // u = 64 (lane 31)

    // d=0 base pointers; address(d) = base + d*SROW.
    const float* pB0 = gB + (PAD - u0 - 1) * SROW + u0;        // blank row t0-1, col u0
    const float* pL0 = gL + (PAD - u0) * SROW + (u0 - 1);      // label row t0,  col u0-1
    const float* pB1 = gB + (PAD - u0 - 2) * SROW + u1;        // blank row t1-1, col u1
    const float* pL1 = gL + (PAD - u0 - 1) * SROW + u0;        // label row t1,  col u0
    const float* pBx = gB + (PAD - 65) * SROW + 64;            // blank row d-65, col 64
    const float* pLx = gL + (PAD - 64) * SROW + 63;            // label row d-64, col 63

    int cw = -1;   // contiguous watermark: rows <= cw confirmed done

    // Opportunistic full scan (serialized case: walks to 255 in ~8 probes).
    {
        int prev = -2;
        while (prev != cw && cw < T_ - 1) { prev = cw; cw = probe32(cnt, cw, lane); }
    }

    float rB0[4], rL0[4], rB1[4], rL1[4], rBx[4], rLx[4];
    int qoff = 0;

    // Prologue: prefetch diagonals q = 1..PF_DEPTH into slots q&3.
#pragma unroll
    for (int q = 1; q <= PF_DEPTH; ++q) {
        const int rowNeed = q < (T_ - 1) ? q : (T_ - 1);
        GATE(rowNeed);
        qoff += SROW;
        const int s = q & 3;
        rB0[s] = __ldcg(pB0 + qoff);
        rL0[s] = __ldcg(pL0 + qoff);
        rB1[s] = __ldcg(pB1 + qoff);
        rL1[s] = __ldcg(pL1 + qoff);
        rBx[s] = __ldcg(pBx + qoff);
        rLx[s] = __ldcg(pLx + qoff);
    }

#define STAGE(K, S)                                                            \
    {                                                                          \
        const int d = d0 + (K);                                                \
        if (d <= dE) {                                                         \
            const float nbr = __shfl_up_sync(0xffffffffu, aO, 1);              \
            const float rEv = lae2(aE + rB0[S], nbr + rL0[S]);                 \
            const float rOv = lae2(aO + rB1[S], aE + rL1[S]);                  \
            const float rXv = lae2(aX + rBx[S], aO + rLx[S]);                  \
            const int t0 = d - u0;                                             \
            const bool actE = (unsigned)t0 < (unsigned)T_;                     \
            const bool actO = (unsigned)(t0 - 1) < (unsigned)T_;               \
            const bool actX = ((unsigned)(d - 64) < (unsigned)T_) && (lane == 31); \
            aE = actE ? rEv : aE;                                              \
            aO = actO ? rOv : aO;                                              \
            aX = actX ? rXv : aX;                                              \
            const int q = d + PF_DEPTH;                                        \
            if (q <= dE) {                                                     \
                const int rowNeed = q < (T_ - 1) ? q : (T_ - 1);               \
                GATE(rowNeed);                                                 \
                qoff += SROW;                                                  \
                rB0[S] = __ldcg(pB0 + qoff);                                   \
                rL0[S] = __ldcg(pL0 + qoff);                                   \
                rB1[S] = __ldcg(pB1 + qoff);                                   \
                rL1[S] = __ldcg(pL1 + qoff);                                   \
                rBx[S] = __ldcg(pBx + qoff);                                   \
                rLx[S] = __ldcg(pLx + qoff);                                   \
            }                                                                  \
        }                                                                      \
    }

    for (int d0 = 1; d0 <= dE; d0 += 4) {
        STAGE(0, 1)
        STAGE(1, 2)
        STAGE(2, 3)
        STAGE(3, 0)
    }
#undef STAGE

    GATE(tE);   // final blank term's row (covers dE==0 too)

    const bool ownE = (uE == u0);
    const bool ownO = (uE == u1);
    const bool ownX = (uE == 64) && (lane == 31);
    if (ownE || ownO || ownX) {
        float alphaF = ownX ? aX : (ownO ? aO : aE);
        if (dE == 0) alphaF = 0.0f;
        const float fb = __ldcg(gB + (PAD + tE) * SROW + uE);
        out[b] = -LN2 * (alphaF + fb);
    }

    __syncwarp();
    // Reset this batch's counters for the next graph replay.
    for (int i = lane; i < T_; i += 32) g_cnt[b * T_ + i] = 0;
}

// ---------------------------------------------------------------------------
extern "C" void kernel_launch(void* const* d_in, const int* in_sizes, int n_in,
                              void* d_out, int out_size) {
    const float* logits = (const float*)d_in[0];
    const int* targets = (const int*)d_in[1];
    const int* srcLen = (const int*)d_in[2];
    const int* tgtLen = (const int*)d_in[3];
    float* out = (float*)d_out;

    lse_kernel<<<LSE_GRID, 256>>>(logits, targets);

    // PDL attrs kept (harmless; pure upside if the overlap engages).
    cudaLaunchConfig_t cfg = {};
    cfg.gridDim = dim3(B_, 1, 1);
    cfg.blockDim = dim3(32, 1, 1);
    cfg.dynamicSmemBytes = 0;
    cfg.stream = 0;
    cudaLaunchAttribute attrs[1];
    attrs[0].id = cudaLaunchAttributeProgrammaticStreamSerialization;
    attrs[0].val.programmaticStreamSerializationAllowed = 1;
    cfg.attrs = attrs;
    cfg.numAttrs = 1;
    cudaLaunchKernelEx(&cfg, dp_kernel, srcLen, tgtLen, out);
}

// round 8
// speedup vs baseline: 1.9203x; 1.4423x over previous
#include <cuda_runtime.h>
#include <cuda_bf16.h>

#define B_ 8
#define T_ 256
#define U_ 65
#define D_ 512
#define BTU_ (B_ * T_ * U_)
#define SROW 66                  // padded row stride (floats)
#define PAD 64                   // zero pad rows front/back in dp smem tiles
#define RTOT (T_ + 2 * PAD)      // 384

#define BIAS 10.0f               // log2-domain bias per step (centers drift)
#define INV_LN2 1.4426950408889634f
#define LN2 0.6931471805599453f

// Scratch: per-(b,t,u) biased probabilities 2^(lp/ln2 + BIAS), stride 66.
__device__ float g_blank[B_ * T_ * SROW];
__device__ float g_label[B_ * T_ * SROW];

__device__ __forceinline__ float ex2f(float x) {
    float y; asm("ex2.approx.ftz.f32 %0, %1;" : "=f"(y) : "f"(x)); return y;
}
__device__ __forceinline__ float lg2f(float x) {
    float y; asm("lg2.approx.ftz.f32 %0, %1;" : "=f"(y) : "f"(x)); return y;
}

// ---------------------------------------------------------------------------
// Kernel 1: per-row logsumexp over D=512 -> biased linear-domain probs.
// One warp per row; HBM-bound (reads 272MB once). Pad column 65 = 0.
// ---------------------------------------------------------------------------
__global__ void __launch_bounds__(256) lse_kernel(const float* __restrict__ logits,
                                                  const int* __restrict__ targets) {
    const int gw = (blockIdx.x * 256 + threadIdx.x) >> 5;
    const int lane = threadIdx.x & 31;
    if (gw >= BTU_) return;

    const float4* row4 = reinterpret_cast<const float4*>(logits + (size_t)gw * D_);
    const float4 v0 = row4[lane];
    const float4 v1 = row4[lane + 32];
    const float4 v2 = row4[lane + 64];
    const float4 v3 = row4[lane + 96];

    float m = v0.x;
    m = fmaxf(m, v0.y); m = fmaxf(m, v0.z); m = fmaxf(m, v0.w);
    m = fmaxf(m, v1.x); m = fmaxf(m, v1.y); m = fmaxf(m, v1.z); m = fmaxf(m, v1.w);
    m = fmaxf(m, v2.x); m = fmaxf(m, v2.y); m = fmaxf(m, v2.z); m = fmaxf(m, v2.w);
    m = fmaxf(m, v3.x); m = fmaxf(m, v3.y); m = fmaxf(m, v3.z); m = fmaxf(m, v3.w);
#pragma unroll
    for (int o = 16; o; o >>= 1) m = fmaxf(m, __shfl_xor_sync(0xffffffffu, m, o));

    float s = 0.f;
    s += __expf(v0.x - m) + __expf(v0.y - m) + __expf(v0.z - m) + __expf(v0.w - m);
    s += __expf(v1.x - m) + __expf(v1.y - m) + __expf(v1.z - m) + __expf(v1.w - m);
    s += __expf(v2.x - m) + __expf(v2.y - m) + __expf(v2.z - m) + __expf(v2.w - m);
    s += __expf(v3.x - m) + __expf(v3.y - m) + __expf(v3.z - m) + __expf(v3.w - m);
#pragma unroll
    for (int o = 16; o; o >>= 1) s += __shfl_xor_sync(0xffffffffu, s, o);

    const float lse = m + __logf(s);
    const float blankLogit = __shfl_sync(0xffffffffu, v3.w, 31);   // element 511

    if (lane == 0) {
        const int b = gw / (T_ * U_);
        const int rem = gw % (T_ * U_);
        const int t = rem / U_;
        const int u = rem % U_;
        const int lbl = (u < U_ - 1) ? targets[b * (U_ - 1) + u] : 0;
        const float labelLogit = __ldg(logits + (size_t)gw * D_ + lbl);
        const int gi = (b * T_ + t) * SROW + u;
        g_blank[gi] = ex2f((blankLogit - lse) * INV_LN2 + BIAS);   // biased prob
        g_label[gi] = ex2f((labelLogit - lse) * INV_LN2 + BIAS);
        if (u == U_ - 1) {            // zero pad column 65 (additive identity)
            g_blank[gi + 1] = 0.0f;
            g_label[gi + 1] = 0.0f;
        }
    }
}

// ---------------------------------------------------------------------------
// Kernel 2: alpha DP in LINEAR domain, one CTA/batch. Zero-padded tiles in
// SMEM; single warp, branchless FMA wavefront: lane l owns u={2l,2l+1},
// lane 31 also u=64. Warp-uniform renormalization every 32 diagonals.
// ---------------------------------------------------------------------------
extern __shared__ float s_dyn[];

__global__ void __launch_bounds__(128) dp_kernel(const int* __restrict__ srcLen,
                                                 const int* __restrict__ tgtLen,
                                                 float* __restrict__ out) {
    const int b = blockIdx.x;
    const int tid = threadIdx.x;

    float* sB = s_dyn;                    // [RTOT * SROW]
    float* sL = s_dyn + RTOT * SROW;

    {   // Zero-fill pad rows, copy valid rows (float4, coalesced).
        const float4 zr = make_float4(0.f, 0.f, 0.f, 0.f);
        float4* sb4 = reinterpret_cast<float4*>(sB);
        float4* sl4 = reinterpret_cast<float4*>(sL);
        const int padQ = (PAD * SROW) / 4;           // 1056
        const int backQ = ((PAD + T_) * SROW) / 4;   // 5280
        for (int i = tid; i < padQ; i += 128) {
            sb4[i] = zr;          sl4[i] = zr;
            sb4[backQ + i] = zr;  sl4[backQ + i] = zr;
        }
        const float4* gb = reinterpret_cast<const float4*>(g_blank + (size_t)b * T_ * SROW);
        const float4* gl = reinterpret_cast<const float4*>(g_label + (size_t)b * T_ * SROW);
#pragma unroll 4
        for (int i = tid; i < (T_ * SROW) / 4; i += 128) {
            sb4[padQ + i] = gb[i];
            sl4[padQ + i] = gl[i];
        }
    }
    __syncthreads();
    if (tid >= 32) return;

    const int lane = tid;
    const int tE = srcLen[b] - 1;
    const int uE = tgtLen[b];
    const int dE = tE + uE;

    const int u0 = 2 * lane;
    const int u1 = u0 + 1;

    // Linear-domain alpha (scaled): A = 2^(alpha_log2 + BIAS*d - expShift)
    float aE = (lane == 0) ? 1.0f : 0.0f;
    float aO = 0.0f;
    float aX = 0.0f;
    float expShift = 0.0f;

    // d-affine load pointers at d = 1 (t0 = 1 - u0), same mapping as round 3.
    const float* pB0 = sB + (PAD + (1 - u0) - 1) * SROW + u0;
    const float* pL0 = sL + (PAD + (1 - u0)) * SROW + (u0 - 1);
    const float* pB1 = sB + (PAD + (1 - u0) - 2) * SROW + u1;
    const float* pL1 = sL + (PAD + (1 - u0) - 1) * SROW + u0;
    const float* pBx = sB + (PAD + 1 - 65) * SROW + 64;
    const float* pLx = sL + (PAD + 1 - 64) * SROW + 63;

    int t0 = 1 - u0;

#pragma unroll 4
    for (int d = 1; d <= dE; ++d) {
        const float xB0 = *pB0;
        const float xL0 = *pL0;
        const float xB1 = *pB1;
        const float xL1 = *pL1;
        const float xBx = *pBx;
        const float xLx = *pLx;

        const float nbr = __shfl_up_sync(0xffffffffu, aO, 1);  // lane0: own aO (×0 pad)

        const float rE = fmaf(aE, xB0, nbr * xL0);
        const float rO = fmaf(aO, xB1, aE * xL1);
        const float rX = fmaf(aX, xBx, aO * xLx);

        const bool actE = (unsigned)t0 < (unsigned)T_;
        const bool actO = (unsigned)(t0 - 1) < (unsigned)T_;
        const bool actX = ((unsigned)(d - 64) < (unsigned)T_) && (lane == 31);

        aE = actE ? rE : aE;
        aO = actO ? rO : aO;
        aX = actX ? rX : aX;

        pB0 += SROW; pL0 += SROW; pB1 += SROW; pL1 += SROW; pBx += SROW; pLx += SROW;
        ++t0;

        if ((d & 31) == 0) {   // warp-uniform renormalization
            float mval = fmaxf(aE, fmaxf(aO, aX));
#pragma unroll
            for (int o = 16; o; o >>= 1) mval = fmaxf(mval, __shfl_xor_sync(0xffffffffu, mval, o));
            const int e = ilogbf(mval);                     // mval > 0 always (lane0 path alive)
            const float s = __uint_as_float((unsigned)(127 - e) << 23);   // 2^-e
            aE *= s; aO *= s; aX *= s;
            expShift += (float)e;
        }
    }

    const bool ownE = (uE == u0);
    const bool ownO = (uE == u1);
    const bool ownX = (uE == 64) && (lane == 31);
    if (ownE || ownO || ownX) {
        float alphaF = ownX ? aX : (ownO ? aO : aE);
        if (dE == 0) alphaF = 1.0f;
        // alpha_log2 = lg2(A) + expShift - BIAS*dE ; blank_log2 = lg2(P) - BIAS
        const float alpha_log2 = lg2f(alphaF) + expShift - BIAS * (float)dE;
        const float fb_log2 = lg2f(sB[(PAD + tE) * SROW + uE]) - BIAS;
        out[b] = -LN2 * (alpha_log2 + fb_log2);
    }
}

// ---------------------------------------------------------------------------
extern "C" void kernel_launch(void* const* d_in, const int* in_sizes, int n_in,
                              void* d_out, int out_size) {
    const float* logits = (const float*)d_in[0];
    const int* targets = (const int*)d_in[1];
    const int* srcLen = (const int*)d_in[2];
    const int* tgtLen = (const int*)d_in[3];
    float* out = (float*)d_out;

    lse_kernel<<<BTU_ / 8, 256>>>(logits, targets);

    const int smemBytes = 2 * RTOT * SROW * (int)sizeof(float);  // 202752 B
    cudaFuncSetAttribute(dp_kernel, cudaFuncAttributeMaxDynamicSharedMemorySize, smemBytes);
    dp_kernel<<<B_, 128, smemBytes>>>(srcLen, tgtLen, out);
}

// round 9
// speedup vs baseline: 2.0877x; 1.0872x over previous
#include <cuda_runtime.h>
#include <cuda_bf16.h>

#define B_ 8
#define T_ 256
#define U_ 65
#define D_ 512
#define BTU_ (B_ * T_ * U_)
#define RSTRIDE 136              // floats per (b,t) row: 4 planes + pad
#define PAD 64                   // zero pad rows in front
#define RTOT 392                 // PAD + T + 72 back-pad rows (covers prefetch)

#define BIAS 10.0f
#define INV_LN2 1.4426950408889634f
#define LN2 0.6931471805599453f

// Row layout (RSTRIDE floats), designed so the DP's 4 strided LDS are
// conflict-free (per-lane bank step -271, gcd(271,32)=1):
//   [  0.. 33] labelOdd : slot0 = 0, slot i = label(t, 2i-1)  (i=1..32); slot33 = 0
//   [ 34.. 66] blankEven: slot i = blank(t, 2i)               (i=0..32)
//   [ 67.. 99] blankOdd : slot i = blank(t, 2i+1)             (i=0..31); slot32 = 0
//   [100..132] labelEven: slot i = label(t, 2i)               (i=0..32)
//   [133..135] pad = 0
// Zero slots are never written (module zero-init keeps them 0 forever).
__device__ float g_probs[B_ * T_ * RSTRIDE];

__device__ __forceinline__ float ex2f(float x) {
    float y; asm("ex2.approx.ftz.f32 %0, %1;" : "=f"(y) : "f"(x)); return y;
}
__device__ __forceinline__ float lg2f(float x) {
    float y; asm("lg2.approx.ftz.f32 %0, %1;" : "=f"(y) : "f"(x)); return y;
}

// ---------------------------------------------------------------------------
// Kernel 1: per-row logsumexp over D=512 -> biased linear-domain probs
// written into the plane-split layout. One warp per row; HBM-bound.
// ---------------------------------------------------------------------------
__global__ void __launch_bounds__(256) lse_kernel(const float* __restrict__ logits,
                                                  const int* __restrict__ targets) {
    const int gw = (blockIdx.x * 256 + threadIdx.x) >> 5;
    const int lane = threadIdx.x & 31;
    if (gw >= BTU_) return;

    const float4* row4 = reinterpret_cast<const float4*>(logits + (size_t)gw * D_);
    const float4 v0 = row4[lane];
    const float4 v1 = row4[lane + 32];
    const float4 v2 = row4[lane + 64];
    const float4 v3 = row4[lane + 96];

    float m = v0.x;
    m = fmaxf(m, v0.y); m = fmaxf(m, v0.z); m = fmaxf(m, v0.w);
    m = fmaxf(m, v1.x); m = fmaxf(m, v1.y); m = fmaxf(m, v1.z); m = fmaxf(m, v1.w);
    m = fmaxf(m, v2.x); m = fmaxf(m, v2.y); m = fmaxf(m, v2.z); m = fmaxf(m, v2.w);
    m = fmaxf(m, v3.x); m = fmaxf(m, v3.y); m = fmaxf(m, v3.z); m = fmaxf(m, v3.w);
#pragma unroll
    for (int o = 16; o; o >>= 1) m = fmaxf(m, __shfl_xor_sync(0xffffffffu, m, o));

    float s = 0.f;
    s += __expf(v0.x - m) + __expf(v0.y - m) + __expf(v0.z - m) + __expf(v0.w - m);
    s += __expf(v1.x - m) + __expf(v1.y - m) + __expf(v1.z - m) + __expf(v1.w - m);
    s += __expf(v2.x - m) + __expf(v2.y - m) + __expf(v2.z - m) + __expf(v2.w - m);
    s += __expf(v3.x - m) + __expf(v3.y - m) + __expf(v3.z - m) + __expf(v3.w - m);
#pragma unroll
    for (int o = 16; o; o >>= 1) s += __shfl_xor_sync(0xffffffffu, s, o);

    const float lse = m + __logf(s);
    const float blankLogit = __shfl_sync(0xffffffffu, v3.w, 31);   // element 511

    if (lane == 0) {
        const int b = gw / (T_ * U_);
        const int rem = gw % (T_ * U_);
        const int t = rem / U_;
        const int u = rem % U_;
        const int lbl = (u < U_ - 1) ? targets[b * (U_ - 1) + u] : 0;
        const float labelLogit = __ldg(logits + (size_t)gw * D_ + lbl);
        const float pb = ex2f((blankLogit - lse) * INV_LN2 + BIAS);
        const float pl = ex2f((labelLogit - lse) * INV_LN2 + BIAS);
        const int base = (b * T_ + t) * RSTRIDE;
        if (u & 1) {
            g_probs[base + 0  + ((u + 1) >> 1)] = pl;   // labelOdd
            g_probs[base + 67 + ((u - 1) >> 1)] = pb;   // blankOdd
        } else {
            g_probs[base + 34  + (u >> 1)] = pb;        // blankEven
            g_probs[base + 100 + (u >> 1)] = pl;        // labelEven
        }
    }
}

// ---------------------------------------------------------------------------
// Kernel 2: linear-domain alpha DP, one CTA/batch. Maskless (zero-padding is
// the mask), conflict-free plane-split smem, 1-deep register prefetch.
// Lane l owns u={2l, 2l+1}; lane 31 also u=64.
// ---------------------------------------------------------------------------
extern __shared__ float s_dyn[];

__global__ void __launch_bounds__(128) dp_kernel(const int* __restrict__ srcLen,
                                                 const int* __restrict__ tgtLen,
                                                 float* __restrict__ out) {
    const int b = blockIdx.x;
    const int tid = threadIdx.x;

    float* sP = s_dyn;   // [RTOT * RSTRIDE]

    {   // Zero pad rows front/back; copy valid rows (float4, contiguous).
        const float4 zr = make_float4(0.f, 0.f, 0.f, 0.f);
        float4* s4 = reinterpret_cast<float4*>(sP);
        const int rowQ = RSTRIDE / 4;                    // 34
        const int frontQ = PAD * rowQ;                   // 2176
        const int backStart = (PAD + T_) * rowQ;         // 10880
        const int backQ = (RTOT - PAD - T_) * rowQ;      // 2448
        for (int i = tid; i < frontQ; i += 128) s4[i] = zr;
        for (int i = tid; i < backQ; i += 128) s4[backStart + i] = zr;
        const float4* g4 = reinterpret_cast<const float4*>(g_probs + (size_t)b * T_ * RSTRIDE);
#pragma unroll 4
        for (int i = tid; i < T_ * rowQ; i += 128) s4[frontQ + i] = g4[i];
    }
    __syncthreads();
    if (tid >= 32) return;

    const int lane = tid;
    const int tE = srcLen[b] - 1;
    const int uE = tgtLen[b];
    const int dE = tE + uE;

    const int u0 = 2 * lane;

    float aE = (lane == 0) ? 1.0f : 0.0f;   // u = u0
    float aO = 0.0f;                        // u = u0+1
    float aX = 0.0f;                        // u = 64 (lane 31's extra cell)
    float expShift = 0.0f;

    // Pointers at diag d=1 (advance +RSTRIDE per diag). Cell (t0=d-u0, u0):
    //  xB0 = blank(t0-1, u0)    -> row t0-1, blankEven slot l
    //  xL0 = label(t0, u0-1)    -> row t0,   labelOdd  slot l (lane0 -> slot0 = 0)
    //  xB1 = blank(t0-2, u0+1)  -> row t0-2, blankOdd  slot l
    //  xL1 = label(t0-1, u0)    -> row t0-1, labelEven slot l
    //  xBx = blank(d-65, 64)    -> row d-65, blankEven slot 32 (broadcast)
    //  xLx = label(d-64, 63)    -> row d-64, labelOdd  slot 32 (broadcast)
    const float* pB0 = sP + (PAD + 0 - u0) * RSTRIDE + 34 + lane;
    const float* pL0 = sP + (PAD + 1 - u0) * RSTRIDE + 0 + lane;
    const float* pB1 = sP + (PAD - 1 - u0) * RSTRIDE + 67 + lane;
    const float* pL1 = sP + (PAD + 0 - u0) * RSTRIDE + 100 + lane;
    const float* pBx = sP + (PAD + 1 - 65) * RSTRIDE + 34 + 32;
    const float* pLx = sP + (PAD + 1 - 64) * RSTRIDE + 0 + 32;

    // Prefetch diag 1.
    float cB0 = *pB0, cL0 = *pL0, cB1 = *pB1, cL1 = *pL1, cBx = *pBx, cLx = *pLx;

#pragma unroll 4
    for (int d = 1; d <= dE; ++d) {
        // Prefetch diag d+1 (pads cover one row beyond dE; values discarded).
        pB0 += RSTRIDE; pL0 += RSTRIDE; pB1 += RSTRIDE;
        pL1 += RSTRIDE; pBx += RSTRIDE; pLx += RSTRIDE;
        const float nB0 = *pB0, nL0 = *pL0, nB1 = *pB1;
        const float nL1 = *pL1, nBx = *pBx, nLx = *pLx;

        const float nbr = __shfl_up_sync(0xffffffffu, aO, 1);  // lane0: x0 pad kills it

        const float rE = fmaf(aE, cB0, nbr * cL0);
        const float rO = fmaf(aO, cB1, aE * cL1);
        const float rX = fmaf(aX, cBx, aO * cLx);   // only lane 31's is meaningful
        aE = rE; aO = rO; aX = rX;

        cB0 = nB0; cL0 = nL0; cB1 = nB1; cL1 = nL1; cBx = nBx; cLx = nLx;

        if ((d & 31) == 0) {   // warp-uniform renormalization (exact, power of 2)
            float mval = fmaxf(aE, fmaxf(aO, aX));
#pragma unroll
            for (int o = 16; o; o >>= 1) mval = fmaxf(mval, __shfl_xor_sync(0xffffffffu, mval, o));
            const int e = ilogbf(mval);
            const float sc = __uint_as_float((unsigned)(127 - e) << 23);   // 2^-e
            aE *= sc; aO *= sc; aX *= sc;
            expShift += (float)e;
        }
    }

    const bool ownE = (uE == u0);
    const bool ownO = (uE == u0 + 1);
    const bool ownX = (uE == 64) && (lane == 31);
    if (ownE || ownO || ownX) {
        float alphaF = ownX ? aX : (ownO ? aO : aE);
        if (dE == 0) alphaF = 1.0f;
        const int rb = (PAD + tE) * RSTRIDE;
        const float fb = (uE & 1) ? sP[rb + 67 + ((uE - 1) >> 1)]
                                  : sP[rb + 34 + (uE >> 1)];
        const float alpha_log2 = lg2f(alphaF) + expShift - BIAS * (float)dE;
        const float fb_log2 = lg2f(fb) - BIAS;
        out[b] = -LN2 * (alpha_log2 + fb_log2);
    }
}

// ---------------------------------------------------------------------------
extern "C" void kernel_launch(void* const* d_in, const int* in_sizes, int n_in,
                              void* d_out, int out_size) {
    const float* logits = (const float*)d_in[0];
    const int* targets = (const int*)d_in[1];
    const int* srcLen = (const int*)d_in[2];
    const int* tgtLen = (const int*)d_in[3];
    float* out = (float*)d_out;

    lse_kernel<<<BTU_ / 8, 256>>>(logits, targets);

    const int smemBytes = RTOT * RSTRIDE * (int)sizeof(float);  // 213248 B
    cudaFuncSetAttribute(dp_kernel, cudaFuncAttributeMaxDynamicSharedMemorySize, smemBytes);
    dp_kernel<<<B_, 128, smemBytes>>>(srcLen, tgtLen, out);
}